// round 12
// baseline (speedup 1.0000x reference)
#include <cuda_runtime.h>
#include <cuda_bf16.h>
#include <math.h>
#include <stdint.h>

#define NROWS  115200           // 6*64*300
#define CDIM   256
#define THDIM  157
#define N2PAD  160              // W23 col pad AND theta K pad (= 4 warps * 5 frags * 8)
#define NPOSE_ 144
#define TILEM  64

// ---------------- scratch (device globals; no allocation) ----------------
__device__ __align__(16) float g_w23f [CDIM * N2PAD];
__device__ __align__(16) float g_cvec [CDIM];
__device__ __align__(16) float g_bvec2[N2PAD];
__device__ __align__(16) float g_tbias[N2PAD];

// Pre-split, pre-swizzled bf16 weights: [chunk64][n][128B row, XOR-swizzled]
__device__ __align__(16) __nv_bfloat16 g_w1a_hi[4 * 256 * 64], g_w1a_lo[4 * 256 * 64]; // N=256,K=256
__device__ __align__(16) __nv_bfloat16 g_w1t_hi[3 * 256 * 64], g_w1t_lo[3 * 256 * 64]; // N=256,K=160(zero-pad to 192)
__device__ __align__(16) __nv_bfloat16 g_w23_hi[4 * N2PAD * 64], g_w23_lo[4 * N2PAD * 64]; // N=160,K=256

// ---------------- helpers (baseline PTX, sm_80-class) ----------------
static __device__ __forceinline__ uint32_t smem_u32(const void* p) {
    uint32_t a;
    asm("{ .reg .u64 t; cvta.to.shared.u64 t, %1; cvt.u32.u64 %0, t; }"
        : "=r"(a) : "l"(p));
    return a;
}
static __device__ __forceinline__ void ldsm_x4(uint32_t* r, uint32_t a) {
    asm volatile("ldmatrix.sync.aligned.m8n8.x4.shared.b16 {%0,%1,%2,%3}, [%4];"
        : "=r"(r[0]), "=r"(r[1]), "=r"(r[2]), "=r"(r[3]) : "r"(a));
}
static __device__ __forceinline__ void ldsm_x2(uint32_t* r, uint32_t a) {
    asm volatile("ldmatrix.sync.aligned.m8n8.x2.shared.b16 {%0,%1}, [%2];"
        : "=r"(r[0]), "=r"(r[1]) : "r"(a));
}
static __device__ __forceinline__ void mma_bf16(float* d, const uint32_t* a,
                                                const uint32_t* b) {
    asm volatile(
        "mma.sync.aligned.m16n8k16.row.col.f32.bf16.bf16.f32 "
        "{%0,%1,%2,%3}, {%4,%5,%6,%7}, {%8,%9}, {%0,%1,%2,%3};"
        : "+f"(d[0]), "+f"(d[1]), "+f"(d[2]), "+f"(d[3])
        : "r"(a[0]), "r"(a[1]), "r"(a[2]), "r"(a[3]), "r"(b[0]), "r"(b[1]));
}
#define CP_ASYNC16(sa, gp) \
    asm volatile("cp.async.cg.shared.global [%0], [%1], 16;" :: "r"(sa), "l"(gp))
#define CP_COMMIT() asm volatile("cp.async.commit_group;" ::: "memory")
#define CP_WAIT0()  asm volatile("cp.async.wait_group 0;" ::: "memory")
#define CP_WAIT1()  asm volatile("cp.async.wait_group 1;" ::: "memory")

__device__ __forceinline__ uint32_t swz(int row, int colbyte) {
    return (uint32_t)(row * 128 + (colbyte ^ ((row & 7) << 4)));
}
static __device__ __forceinline__ unsigned short bf_hi(float v) {
    return __bfloat16_as_ushort(__float2bfloat16_rn(v));
}
static __device__ __forceinline__ float bf_val(unsigned short u) {
    return __bfloat162float(__ushort_as_bfloat16(u));
}

// ---------------- weight / vector prep ----------------
__global__ void prep_w23(const float* __restrict__ W2, const float* __restrict__ W3)
{
    int k = blockIdx.x;          // 0..255
    int n = threadIdx.x;         // 0..159
    float acc = 0.f;
    if (n < THDIM)
        for (int j = 0; j < CDIM; j++)
            acc = fmaf(W2[k * CDIM + j], W3[j * THDIM + n], acc);
    g_w23f[k * N2PAD + n] = (n < THDIM) ? acc : 0.f;
}

__global__ void prep_vecs(const float* __restrict__ W1, const float* __restrict__ b2,
                          const float* __restrict__ W3, const float* __restrict__ b3,
                          const float* __restrict__ cr, const float* __restrict__ sh,
                          const float* __restrict__ cam)
{
    __shared__ float th0[THDIM];
    int t = threadIdx.x;   // 0..255
    if (t < THDIM) {
        float v;
        if (t < NPOSE_)           v = cr[t];
        else if (t < NPOSE_ + 10) v = sh[t - NPOSE_];
        else                      v = cam[t - NPOSE_ - 10];
        th0[t] = v;
    }
    __syncthreads();
    {
        float acc = 0.f;
        for (int j = 0; j < THDIM; j++)
            acc = fmaf(th0[j], W1[(size_t)(CDIM + j) * CDIM + t], acc);
        g_cvec[t] = acc;
    }
    if (t < N2PAD) {
        float bv = 0.f;
        if (t < THDIM) {
            for (int j = 0; j < CDIM; j++)
                bv = fmaf(b2[j], W3[j * THDIM + t], bv);
            bv += b3[t];
        }
        g_bvec2[t] = bv;
        g_tbias[t] = bv + ((t < THDIM) ? th0[t] : 0.f);
    }
}

static __device__ __forceinline__ void put_w(__nv_bfloat16* hiArr, __nv_bfloat16* loArr,
                                             int Nrows, int k, int n, float v)
{
    unsigned short hb = bf_hi(v);
    unsigned short lb = bf_hi(v - bf_val(hb));
    int chunk = k >> 6, kc = k & 63;
    size_t byte = (size_t)chunk * ((size_t)Nrows * 128) + swz(n, kc * 2);
    *(unsigned short*)((char*)hiArr + byte) = hb;
    *(unsigned short*)((char*)loArr + byte) = lb;
}

__global__ void conv_w1a(const float* __restrict__ W1)
{
    int idx = blockIdx.x * blockDim.x + threadIdx.x;
    if (idx >= 256 * 256) return;
    int k = idx >> 8, n = idx & 255;
    put_w(g_w1a_hi, g_w1a_lo, 256, k, n, W1[(size_t)k * CDIM + n]);
}
__global__ void conv_w23k(void)
{
    int idx = blockIdx.x * blockDim.x + threadIdx.x;
    if (idx >= 256 * N2PAD) return;
    int k = idx / N2PAD, n = idx % N2PAD;
    put_w(g_w23_hi, g_w23_lo, N2PAD, k, n, g_w23f[k * N2PAD + n]);
}
__global__ void conv_w1t(const float* __restrict__ W1)
{
    int idx = blockIdx.x * blockDim.x + threadIdx.x;
    if (idx >= 192 * 256) return;               // zero-fill chunk 2 upper half too
    int k = idx >> 8, n = idx & 255;
    float v = (k < THDIM) ? W1[(size_t)(CDIM + k) * CDIM + n] : 0.f;
    put_w(g_w1t_hi, g_w1t_lo, 256, k, n, v);
}

// ---------------- MMA passes (SC = k16-steps in this chunk) ----------------
template<int NF, int SC>
__device__ __forceinline__ void pass1s(uint32_t aHi, uint32_t aLo, uint32_t bHi,
                                       float (*acc)[4], int lane, int wm, int wn)
{
#pragma unroll
    for (int s = 0; s < SC; s++) {
        uint32_t Ah[4], Al[4], Bf[NF][2];
        int ca = s * 32 + ((lane >> 4) << 4);
        int cb = s * 32 + (((lane >> 3) & 1) << 4);
        int row = wm * 16 + (lane & 15);
        uint32_t aoff = (uint32_t)(row * 128 + (ca ^ ((row & 7) << 4)));
        ldsm_x4(Ah, aHi + aoff);
        ldsm_x4(Al, aLo + aoff);
#pragma unroll
        for (int nf = 0; nf < NF; nf++) {
            int rn = wn * (NF * 8) + nf * 8 + (lane & 7);
            uint32_t off = (uint32_t)(rn * 128 + (cb ^ ((lane & 7) << 4)));
            ldsm_x2(Bf[nf], bHi + off);
        }
#pragma unroll
        for (int nf = 0; nf < NF; nf++) mma_bf16(acc[nf], Ah, Bf[nf]);
#pragma unroll
        for (int nf = 0; nf < NF; nf++) mma_bf16(acc[nf], Al, Bf[nf]);
    }
}

template<int NF, int SC>
__device__ __forceinline__ void pass2s(uint32_t aHi, uint32_t bLo,
                                       float (*acc)[4], int lane, int wm, int wn)
{
#pragma unroll
    for (int s = 0; s < SC; s++) {
        uint32_t Ah[4], Bf[NF][2];
        int ca = s * 32 + ((lane >> 4) << 4);
        int cb = s * 32 + (((lane >> 3) & 1) << 4);
        int row = wm * 16 + (lane & 15);
        uint32_t aoff = (uint32_t)(row * 128 + (ca ^ ((row & 7) << 4)));
        ldsm_x4(Ah, aHi + aoff);
#pragma unroll
        for (int nf = 0; nf < NF; nf++) {
            int rn = wn * (NF * 8) + nf * 8 + (lane & 7);
            uint32_t off = (uint32_t)(rn * 128 + (cb ^ ((lane & 7) << 4)));
            ldsm_x2(Bf[nf], bLo + off);
        }
#pragma unroll
        for (int nf = 0; nf < NF; nf++) mma_bf16(acc[nf], Ah, Bf[nf]);
    }
}

// Single-pass chunk for N=160 phases: 3 MMAs per (s, nf), both B splits resident.
template<int SC>
__device__ __forceinline__ void chunk160(uint32_t aHi, uint32_t aLo,
                                         uint32_t bH, uint32_t bL,
                                         float (*acc)[4], int lane, int wm, int wn)
{
#pragma unroll
    for (int s = 0; s < SC; s++) {
        uint32_t Ah[4], Al[4], Bh[5][2], Bl[5][2];
        int ca = s * 32 + ((lane >> 4) << 4);
        int cb = s * 32 + (((lane >> 3) & 1) << 4);
        int row = wm * 16 + (lane & 15);
        uint32_t aoff = (uint32_t)(row * 128 + (ca ^ ((row & 7) << 4)));
        ldsm_x4(Ah, aHi + aoff);
        ldsm_x4(Al, aLo + aoff);
#pragma unroll
        for (int nf = 0; nf < 5; nf++) {
            int rn = wn * 40 + nf * 8 + (lane & 7);
            uint32_t off = (uint32_t)(rn * 128 + (cb ^ ((lane & 7) << 4)));
            ldsm_x2(Bh[nf], bH + off);
            ldsm_x2(Bl[nf], bL + off);
        }
#pragma unroll
        for (int nf = 0; nf < 5; nf++) mma_bf16(acc[nf], Ah, Bh[nf]);
#pragma unroll
        for (int nf = 0; nf < 5; nf++) mma_bf16(acc[nf], Ah, Bl[nf]);
#pragma unroll
        for (int nf = 0; nf < 5; nf++) mma_bf16(acc[nf], Al, Bh[nf]);
    }
}

// ---------------- mega kernel ----------------
// One 512-thread CTA handles a 64-row tile end-to-end, including rot6d output.
// SMEM (212992B): [0,64K) XW1 fp32 (later: final theta fp32, stride 160)
//                 [64K,128K) U/THS bf16 split (hi 64K+c*8K, lo 96K+c*8K; K1 A-dbuf overlay)
//                 [128K,208K) B region: N=256 pass-split slots S0,S1 (32K each)
//                             N=160 single-pass slots buf*40K + split*20K
__global__ void __launch_bounds__(512, 1)
mega_kernel(const float* __restrict__ x,
            const __nv_bfloat16* __restrict__ w1a_h, const __nv_bfloat16* __restrict__ w1a_l,
            const __nv_bfloat16* __restrict__ w1t_h, const __nv_bfloat16* __restrict__ w1t_l,
            const __nv_bfloat16* __restrict__ w23_h, const __nv_bfloat16* __restrict__ w23_l,
            const float* __restrict__ b1v, const float* __restrict__ cvec,
            const float* __restrict__ tbias, const float* __restrict__ bvec2,
            float* __restrict__ out)
{
    extern __shared__ char smem[];
    const uint32_t sb = smem_u32(smem);
    const int tid = threadIdx.x, lane = tid & 31, wid = tid >> 5;
    const int wm = wid & 3, wn = wid >> 2;           // 4m x 4n warps
    const int bm = blockIdx.x * TILEM;

    const uint32_t BB  = sb + 131072;
    const uint32_t S0  = BB, S1 = BB + 32768;        // N=256 slots
    const uint32_t UHI = sb + 65536, ULO = sb + 98304;
    const int er = wm * 16 + (lane >> 2);

    auto store_u = [&](int row, int col, float ux, float uy) {
        unsigned short h0 = bf_hi(ux), h1 = bf_hi(uy);
        unsigned short l0 = bf_hi(ux - bf_val(h0)), l1 = bf_hi(uy - bf_val(h1));
        uint32_t off = (uint32_t)((col >> 6) * 8192) + swz(row, (col & 63) * 2);
        *reinterpret_cast<uint32_t*>(smem + 65536 + off) = (uint32_t)h0 | ((uint32_t)h1 << 16);
        *reinterpret_cast<uint32_t*>(smem + 98304 + off) = (uint32_t)l0 | ((uint32_t)l1 << 16);
    };
    // B copy helpers
    auto cpyB32 = [&](const __nv_bfloat16* src, int c, uint32_t dst) {
        const char* s = (const char*)src + (size_t)c * 32768;
#pragma unroll
        for (int i = 0; i < 4; i++) {
            int j = tid + i * 512;
            CP_ASYNC16(dst + j * 16, s + (size_t)j * 16);
        }
    };
    auto cpyB20 = [&](int c, int buf) {      // W23 chunk, both splits
        const char* sh = (const char*)w23_h + (size_t)c * 20480;
        const char* sl = (const char*)w23_l + (size_t)c * 20480;
        uint32_t dh = BB + buf * 40960, dl = dh + 20480;
#pragma unroll
        for (int i = 0; i < 3; i++) {
            int j = tid + i * 512;
            if (j < 1280) {
                CP_ASYNC16(dh + j * 16, sh + (size_t)j * 16);
                CP_ASYNC16(dl + j * 16, sl + (size_t)j * 16);
            }
        }
    };

    float th[5][4];
#pragma unroll
    for (int i = 0; i < 5; i++)
#pragma unroll
        for (int q = 0; q < 4; q++) th[i][q] = 0.f;

    // ======== K1 phase 1: xw1 = x @ W1a + b1 (A streamed from global) ========
    {
        float acc[8][4];
#pragma unroll
        for (int i = 0; i < 8; i++)
#pragma unroll
            for (int q = 0; q < 4; q++) acc[i][q] = 0.f;

        float4 aR[2];
        auto loadAg = [&](int c) {
#pragma unroll
            for (int i = 0; i < 2; i++) {
                int idx = tid + i * 512;
                int row = idx >> 4, f4 = idx & 15;
                aR[i] = *reinterpret_cast<const float4*>(
                    x + (size_t)(bm + row) * CDIM + (c << 6) + f4 * 4);
            }
        };
        auto storeA = [&](int buf) {
            char* hi = smem + 65536 + buf * 16384;
            char* lo = hi + 8192;
#pragma unroll
            for (int i = 0; i < 2; i++) {
                int idx = tid + i * 512;
                int row = idx >> 4, f4 = idx & 15;
                float4 v = aR[i];
                unsigned short h0 = bf_hi(v.x), h1 = bf_hi(v.y), h2 = bf_hi(v.z), h3 = bf_hi(v.w);
                unsigned short l0 = bf_hi(v.x - bf_val(h0)), l1 = bf_hi(v.y - bf_val(h1));
                unsigned short l2 = bf_hi(v.z - bf_val(h2)), l3 = bf_hi(v.w - bf_val(h3));
                uint2 hv = make_uint2((uint32_t)h0 | ((uint32_t)h1 << 16),
                                      (uint32_t)h2 | ((uint32_t)h3 << 16));
                uint2 lv = make_uint2((uint32_t)l0 | ((uint32_t)l1 << 16),
                                      (uint32_t)l2 | ((uint32_t)l3 << 16));
                uint32_t off = swz(row, f4 * 8);
                *reinterpret_cast<uint2*>(hi + off) = hv;
                *reinterpret_cast<uint2*>(lo + off) = lv;
            }
        };

        cpyB32(w1a_h, 0, S0); CP_COMMIT();
        loadAg(0); storeA(0);
        CP_WAIT0(); __syncthreads();
#pragma unroll
        for (int c = 0; c < 4; c++) {
            cpyB32(w1a_l, c, S1); CP_COMMIT();
            if (c < 3) loadAg(c + 1);
            uint32_t aHi = sb + 65536 + (c & 1) * 16384, aLo = aHi + 8192;
            pass1s<8, 4>(aHi, aLo, S0, acc, lane, wm, wn);
            __syncthreads();
            if (c < 3) { cpyB32(w1a_h, c + 1, S0); CP_COMMIT(); CP_WAIT1(); }
            else       { CP_WAIT0(); }
            __syncthreads();
            pass2s<8, 4>(aHi, S1, acc, lane, wm, wn);
            if (c < 3) storeA((c + 1) & 1);
            CP_WAIT0();
            __syncthreads();
        }
        // epilogue: XW1 fp32 (smem) + U = relu(xw1 + cvec)
#pragma unroll
        for (int nf = 0; nf < 8; nf++) {
            int col = wn * 64 + nf * 8 + (lane & 3) * 2;
            float bx = __ldg(b1v + col), by = __ldg(b1v + col + 1);
            float2 v0 = make_float2(acc[nf][0] + bx, acc[nf][1] + by);
            float2 v1 = make_float2(acc[nf][2] + bx, acc[nf][3] + by);
            *reinterpret_cast<float2*>(smem + ((size_t)er * 256 + col) * 4) = v0;
            *reinterpret_cast<float2*>(smem + ((size_t)(er + 8) * 256 + col) * 4) = v1;
            float cx = __ldg(cvec + col), cy = __ldg(cvec + col + 1);
            store_u(er,     col, fmaxf(v0.x + cx, 0.f), fmaxf(v0.y + cy, 0.f));
            store_u(er + 8, col, fmaxf(v1.x + cx, 0.f), fmaxf(v1.y + cy, 0.f));
        }
        __syncthreads();
    }

    // phase-2 runner: acc2 = U @ W23 (N=160, K=256, single-pass dbuf)
    auto run_p2 = [&](float (*ac2)[4]) {
        cpyB20(0, 0); CP_COMMIT();
        CP_WAIT0(); __syncthreads();
#pragma unroll
        for (int c = 0; c < 4; c++) {
            if (c < 3) { cpyB20(c + 1, (c + 1) & 1); CP_COMMIT(); }
            uint32_t bH = BB + (c & 1) * 40960, bL = bH + 20480;
            chunk160<4>(UHI + c * 8192, ULO + c * 8192, bH, bL, ac2, lane, wm, wn);
            CP_WAIT0();
            __syncthreads();
        }
    };

    // ======== K1 phase 2: theta = U @ W23 + tbias ========
    {
        float ac2[5][4];
#pragma unroll
        for (int i = 0; i < 5; i++)
#pragma unroll
            for (int q = 0; q < 4; q++) ac2[i][q] = 0.f;
        run_p2(ac2);
#pragma unroll
        for (int nf = 0; nf < 5; nf++) {
            int col = wn * 40 + nf * 8 + (lane & 3) * 2;
            float bx = __ldg(tbias + col), by = __ldg(tbias + col + 1);
            th[nf][0] = ac2[nf][0] + bx;  th[nf][1] = ac2[nf][1] + by;
            th[nf][2] = ac2[nf][2] + bx;  th[nf][3] = ac2[nf][3] + by;
            store_u(er,     col, th[nf][0], th[nf][1]);
            store_u(er + 8, col, th[nf][2], th[nf][3]);
        }
        __syncthreads();
    }

    // ======== iterations 2, 3 ========
#pragma unroll 1
    for (int it = 0; it < 2; it++) {
        // phase 1: h = relu(xw1 + theta @ W1t); A = THS chunks {4,4,2} k16-steps
        {
            float acc[8][4];
#pragma unroll
            for (int i = 0; i < 8; i++)
#pragma unroll
                for (int q = 0; q < 4; q++) acc[i][q] = 0.f;

            cpyB32(w1t_h, 0, S0); CP_COMMIT();
            CP_WAIT0(); __syncthreads();
#pragma unroll
            for (int c = 0; c < 3; c++) {
                cpyB32(w1t_l, c, S1); CP_COMMIT();
                uint32_t aHi = UHI + c * 8192, aLo = ULO + c * 8192;
                if (c < 2) pass1s<8, 4>(aHi, aLo, S0, acc, lane, wm, wn);
                else       pass1s<8, 2>(aHi, aLo, S0, acc, lane, wm, wn);
                __syncthreads();
                if (c < 2) { cpyB32(w1t_h, c + 1, S0); CP_COMMIT(); CP_WAIT1(); }
                else       { CP_WAIT0(); }
                __syncthreads();
                if (c < 2) pass2s<8, 4>(aHi, S1, acc, lane, wm, wn);
                else       pass2s<8, 2>(aHi, S1, acc, lane, wm, wn);
                CP_WAIT0();
                __syncthreads();
            }
#pragma unroll
            for (int nf = 0; nf < 8; nf++) {
                int col = wn * 64 + nf * 8 + (lane & 3) * 2;
                float2 r0 = *reinterpret_cast<const float2*>(smem + ((size_t)er * 256 + col) * 4);
                float2 r1 = *reinterpret_cast<const float2*>(smem + ((size_t)(er + 8) * 256 + col) * 4);
                store_u(er,     col, fmaxf(acc[nf][0] + r0.x, 0.f), fmaxf(acc[nf][1] + r0.y, 0.f));
                store_u(er + 8, col, fmaxf(acc[nf][2] + r1.x, 0.f), fmaxf(acc[nf][3] + r1.y, 0.f));
            }
            __syncthreads();
        }
        // phase 2: theta += h @ W23 + bvec2
        {
            float ac2[5][4];
#pragma unroll
            for (int i = 0; i < 5; i++)
#pragma unroll
                for (int q = 0; q < 4; q++) ac2[i][q] = 0.f;
            run_p2(ac2);
#pragma unroll
            for (int nf = 0; nf < 5; nf++) {
                int col = wn * 40 + nf * 8 + (lane & 3) * 2;
                float bx = __ldg(bvec2 + col), by = __ldg(bvec2 + col + 1);
                th[nf][0] += ac2[nf][0] + bx;  th[nf][1] += ac2[nf][1] + by;
                th[nf][2] += ac2[nf][2] + bx;  th[nf][3] += ac2[nf][3] + by;
                if (it == 0) {
                    store_u(er,     col, th[nf][0], th[nf][1]);
                    store_u(er + 8, col, th[nf][2], th[nf][3]);
                } else {
                    // final theta fp32 into (dead) XW1 region, stride 160
                    *reinterpret_cast<float2*>(smem + ((size_t)er * 160 + col) * 4) =
                        make_float2(th[nf][0], th[nf][1]);
                    *reinterpret_cast<float2*>(smem + ((size_t)(er + 8) * 160 + col) * 4) =
                        make_float2(th[nf][2], th[nf][3]);
                }
            }
            __syncthreads();
        }
    }

    // ======== fused output epilogue: rot6d + betas/cam ========
    const float* ths = reinterpret_cast<const float*>(smem);
#pragma unroll
    for (int k2 = 0; k2 < 3; k2++) {
        int idx = tid + k2 * 512;            // 0..1535 = 64 rows * 24 joints
        int row = idx / 24, j = idx % 24;
        const float* p = ths + row * 160 + j * 6;
        float a1x = p[0], a2x = p[1];
        float a1y = p[2], a2y = p[3];
        float a1z = p[4], a2z = p[5];

        float n1 = fmaxf(sqrtf(a1x * a1x + a1y * a1y + a1z * a1z), 1e-12f);
        float b1x = a1x / n1, b1y = a1y / n1, b1z = a1z / n1;

        float d = b1x * a2x + b1y * a2y + b1z * a2z;
        float u2x = a2x - d * b1x, u2y = a2y - d * b1y, u2z = a2z - d * b1z;
        float n2 = fmaxf(sqrtf(u2x * u2x + u2y * u2y + u2z * u2z), 1e-12f);
        float b2x = u2x / n2, b2y = u2y / n2, b2z = u2z / n2;

        float b3x = b1y * b2z - b1z * b2y;
        float b3y = b1z * b2x - b1x * b2z;
        float b3z = b1x * b2y - b1y * b2x;

        float* o = out + ((size_t)(bm + row) * 24 + j) * 9;
        o[0] = b1x; o[1] = b2x; o[2] = b3x;
        o[3] = b1y; o[4] = b2y; o[5] = b3y;
        o[6] = b1z; o[7] = b2z; o[8] = b3z;
    }
    {
        const size_t OB  = (size_t)NROWS * 216;
        const size_t OB2 = OB + (size_t)NROWS * 10;
        for (int i = tid; i < TILEM * 13; i += 512) {
            int row = i / 13, k = i % 13;
            float v = ths[row * 160 + NPOSE_ + k];
            if (k < 10) out[OB + (size_t)(bm + row) * 10 + k] = v;
            else        out[OB2 + (size_t)(bm + row) * 3 + (k - 10)] = v;
        }
    }
}

// ---------------------------------------------------------------------------
extern "C" void kernel_launch(void* const* d_in, const int* in_sizes, int n_in,
                              void* d_out, int out_size)
{
    const float* x   = (const float*)d_in[0];
    // d_in[1] = pred_class (unused)
    const float* W1  = (const float*)d_in[2];
    const float* b1  = (const float*)d_in[3];
    const float* W2  = (const float*)d_in[4];
    const float* b2  = (const float*)d_in[5];
    const float* W3  = (const float*)d_in[6];
    const float* b3  = (const float*)d_in[7];
    const float* cr  = (const float*)d_in[8];
    const float* sh  = (const float*)d_in[9];
    const float* cam = (const float*)d_in[10];
    float* out = (float*)d_out;

    float *p_cvec, *p_bvec2, *p_tbias;
    cudaGetSymbolAddress((void**)&p_cvec,  g_cvec);
    cudaGetSymbolAddress((void**)&p_bvec2, g_bvec2);
    cudaGetSymbolAddress((void**)&p_tbias, g_tbias);
    __nv_bfloat16 *w1a_h, *w1a_l, *w23_h, *w23_l, *w1t_h, *w1t_l;
    cudaGetSymbolAddress((void**)&w1a_h, g_w1a_hi);
    cudaGetSymbolAddress((void**)&w1a_l, g_w1a_lo);
    cudaGetSymbolAddress((void**)&w23_h, g_w23_hi);
    cudaGetSymbolAddress((void**)&w23_l, g_w23_lo);
    cudaGetSymbolAddress((void**)&w1t_h, g_w1t_hi);
    cudaGetSymbolAddress((void**)&w1t_l, g_w1t_lo);

    const size_t SMEM = 212992;     // 208KB
    cudaFuncSetAttribute(mega_kernel, cudaFuncAttributeMaxDynamicSharedMemorySize, SMEM);

    prep_w23<<<CDIM, N2PAD>>>(W2, W3);
    prep_vecs<<<1, CDIM>>>(W1, b2, W3, b3, cr, sh, cam);
    conv_w1a<<<(256 * 256 + 255) / 256, 256>>>(W1);
    conv_w23k<<<(256 * N2PAD + 255) / 256, 256>>>();
    conv_w1t<<<(192 * 256 + 255) / 256, 256>>>(W1);

    mega_kernel<<<NROWS / TILEM, 512, SMEM>>>(
        x, w1a_h, w1a_l, w1t_h, w1t_l, w23_h, w23_l,
        b1, p_cvec, p_tbias, p_bvec2, out);
}